// round 3
// baseline (speedup 1.0000x reference)
#include <cuda_runtime.h>
#include <math.h>

// Problem constants (fixed by the dataset)
#define E_MAX   100000
#define ND_MAX  10000
#define C_DIM   128
#define MLP_IN  64
#define HID     128
#define WOUT    512      // 4 * 128
#define SH_DIM  16
#define OUT_COLS 2048    // 128 * (1+3+5+7)

// -------- device scratch (static allocation: allowed) --------
__device__ int   g_count [ND_MAX];
__device__ int   g_cursor[ND_MAX];
__device__ int   g_offset[ND_MAX + 1];
__device__ int   g_elist [E_MAX];
__device__ float g_tpw   [(size_t)E_MAX * WOUT];   // 204.8 MB edge MLP output

// ==================== CSR build ====================

__global__ void zero_kernel(int nd) {
    int i = blockIdx.x * blockDim.x + threadIdx.x;
    if (i < nd) { g_count[i] = 0; g_cursor[i] = 0; }
}

__global__ void hist_kernel(const int* __restrict__ dst, int E) {
    int e = blockIdx.x * blockDim.x + threadIdx.x;
    if (e < E) atomicAdd(&g_count[dst[e]], 1);
}

// single-block scan over nd (<= 10000) counters -> exclusive offsets
__global__ void scan_kernel(int nd) {
    __shared__ int s[1024];
    int t = threadIdx.x;
    int chunk = (nd + 1023) / 1024;
    int beg = t * chunk;
    int end = min(beg + chunk, nd);
    int sum = 0;
    for (int i = beg; i < end; i++) sum += g_count[i];
    s[t] = sum;
    __syncthreads();
    // Hillis-Steele inclusive scan
    for (int off = 1; off < 1024; off <<= 1) {
        int v = (t >= off) ? s[t - off] : 0;
        __syncthreads();
        s[t] += v;
        __syncthreads();
    }
    int run = s[t] - sum;          // exclusive base for this thread's chunk
    for (int i = beg; i < end; i++) {
        g_offset[i] = run;
        run += g_count[i];
    }
    if (t == 1023) g_offset[nd] = s[1023];
}

__global__ void fill_kernel(const int* __restrict__ dst, int E) {
    int e = blockIdx.x * blockDim.x + threadIdx.x;
    if (e < E) {
        int d = dst[e];
        int p = atomicAdd(&g_cursor[d], 1);
        g_elist[g_offset[d] + p] = e;
    }
}

// ==================== fused edge MLP ====================
// tpw[e][:] = silu(emb[e] @ (W1/8)) @ (W2/sqrt(128))
// 32 edges per block, 256 threads, register micro-tile 4 edges x 16 outputs.
// smem: emb tile 8KB | W1 32KB | Ht (transposed, padded) 16.5KB | W2 K-chunk 32KB

#define EPB 32
#define SM_EMB 0
#define SM_W1  (EPB * MLP_IN)                       // 2048
#define SM_HT  (SM_W1 + MLP_IN * HID)               // 2048 + 8192 = 10240
#define HT_PAD 33
#define SM_W2  (SM_HT + HID * HT_PAD)               // + 4224 = 14464
#define SM_TOTAL (SM_W2 + 16 * WOUT)                // + 8192 = 22656 floats

__global__ __launch_bounds__(256, 2)
void mlp_kernel(const float* __restrict__ emb,
                const float* __restrict__ W1,
                const float* __restrict__ W2,
                int E) {
    extern __shared__ float sm[];
    float* s_emb = sm + SM_EMB;
    float* s_W1  = sm + SM_W1;
    float* s_Ht  = sm + SM_HT;   // [HID][EPB] padded to HT_PAD
    float* s_W2  = sm + SM_W2;   // [16][WOUT]

    int tid = threadIdx.x;
    int e0  = blockIdx.x * EPB;

    // load emb tile (zero-fill tail edges)
    for (int i = tid; i < EPB * MLP_IN; i += 256) {
        int e = i >> 6, k = i & 63;
        int ge = e0 + e;
        s_emb[i] = (ge < E) ? emb[(size_t)ge * MLP_IN + k] : 0.f;
    }
    // load W1 pre-scaled by 1/sqrt(64)
    for (int i = tid; i < MLP_IN * HID; i += 256)
        s_W1[i] = W1[i] * 0.125f;
    __syncthreads();

    // phase B: H = silu(emb @ W1s), stored transposed Ht[j][e]
    for (int i = tid; i < EPB * HID; i += 256) {
        int e = i >> 7, j = i & 127;
        const float* er = &s_emb[e * MLP_IN];
        float acc = 0.f;
#pragma unroll
        for (int k = 0; k < MLP_IN; k++)
            acc += er[k] * s_W1[k * HID + j];
        float sg = 1.f / (1.f + __expf(-acc));
        s_Ht[j * HT_PAD + e] = acc * sg;
    }

    // phase C: TPW = H @ W2s, K=128 in chunks of 16 rows
    int tx = tid & 31, ty = tid >> 5;   // warp = ty; edges ty*4..+3, outputs tx*16..+15
    float acc[4][16];
#pragma unroll
    for (int a = 0; a < 4; a++)
#pragma unroll
        for (int b = 0; b < 16; b++) acc[a][b] = 0.f;

    const float w2s = 0.08838834764831845f;  // 1/sqrt(128)
    for (int kb = 0; kb < HID; kb += 16) {
        __syncthreads();
        for (int i = tid; i < 16 * WOUT; i += 256) {
            int r = i >> 9, m = i & 511;
            s_W2[i] = W2[(size_t)(kb + r) * WOUT + m] * w2s;
        }
        __syncthreads();
#pragma unroll
        for (int r = 0; r < 16; r++) {
            // broadcast loads (all lanes in a warp share ty)
            float h0 = s_Ht[(kb + r) * HT_PAD + ty * 4 + 0];
            float h1 = s_Ht[(kb + r) * HT_PAD + ty * 4 + 1];
            float h2 = s_Ht[(kb + r) * HT_PAD + ty * 4 + 2];
            float h3 = s_Ht[(kb + r) * HT_PAD + ty * 4 + 3];
            const float4* wr4 = (const float4*)&s_W2[r * WOUT + tx * 16];
#pragma unroll
            for (int q = 0; q < 4; q++) {
                float4 w = wr4[q];
                float wv[4] = {w.x, w.y, w.z, w.w};
#pragma unroll
                for (int j = 0; j < 4; j++) {
                    int b = q * 4 + j;
                    acc[0][b] += h0 * wv[j];
                    acc[1][b] += h1 * wv[j];
                    acc[2][b] += h2 * wv[j];
                    acc[3][b] += h3 * wv[j];
                }
            }
        }
    }

    // store 4 edges x 16 outputs (float4 vectorized)
#pragma unroll
    for (int a = 0; a < 4; a++) {
        int e = e0 + ty * 4 + a;
        if (e < E) {
            float4* o4 = (float4*)&g_tpw[(size_t)e * WOUT + tx * 16];
#pragma unroll
            for (int q = 0; q < 4; q++)
                o4[q] = make_float4(acc[a][q*4], acc[a][q*4+1], acc[a][q*4+2], acc[a][q*4+3]);
        }
    }
}

// ==================== per-dst gather (no float atomics) ====================
// block = one dst node, 128 threads (thread = channel c), 16 accumulators in regs.

__global__ __launch_bounds__(128)
void gather_kernel(const float* __restrict__ xsrc,
                   const float* __restrict__ sh,
                   const int*   __restrict__ src,
                   float*       __restrict__ out) {
    int d = blockIdx.x;
    int c = threadIdx.x;   // 0..127
    __shared__ float s_sh[SH_DIM];
    __shared__ float s_out[OUT_COLS];

    float acc[16];
#pragma unroll
    for (int i = 0; i < 16; i++) acc[i] = 0.f;

    int beg = g_offset[d], end = g_offset[d + 1];
    for (int k = beg; k < end; k++) {
        int e = g_elist[k];
        __syncthreads();               // protect s_sh reuse from prev iter
        if (c < SH_DIM) s_sh[c] = sh[(size_t)e * SH_DIM + c];
        __syncthreads();
        int s = src[e];
        float xs = xsrc[(size_t)s * C_DIM + c];
        const float* tp = &g_tpw[(size_t)e * WOUT];
        float t0 = tp[c]       * xs;
        float t1 = tp[128 + c] * xs;
        float t2 = tp[256 + c] * xs;
        float t3 = tp[384 + c] * xs;
        acc[0] += t0 * s_sh[0];
#pragma unroll
        for (int m = 0; m < 3; m++) acc[1 + m] += t1 * s_sh[1 + m];
#pragma unroll
        for (int m = 0; m < 5; m++) acc[4 + m] += t2 * s_sh[4 + m];
#pragma unroll
        for (int m = 0; m < 7; m++) acc[9 + m] += t3 * s_sh[9 + m];
    }

    // stage to smem in final layout (concat over l, inner index c*d+m)
    s_out[c] = acc[0];
#pragma unroll
    for (int m = 0; m < 3; m++) s_out[128  + c * 3 + m] = acc[1 + m];
#pragma unroll
    for (int m = 0; m < 5; m++) s_out[512  + c * 5 + m] = acc[4 + m];
#pragma unroll
    for (int m = 0; m < 7; m++) s_out[1152 + c * 7 + m] = acc[9 + m];
    __syncthreads();

    // coalesced float4 writeback
    float4* o4 = (float4*)(out + (size_t)d * OUT_COLS);
    const float4* s4 = (const float4*)s_out;
    for (int i = c; i < OUT_COLS / 4; i += 128) o4[i] = s4[i];
}

// ==================== launch ====================

extern "C" void kernel_launch(void* const* d_in, const int* in_sizes, int n_in,
                              void* d_out, int out_size) {
    const float* xsrc = (const float*)d_in[0];   // src_features (N_SRC, 128)
    const float* sh   = (const float*)d_in[1];   // edge_sh (E, 16)
    const float* emb  = (const float*)d_in[2];   // edge_emb (E, 64)
    const float* W1   = (const float*)d_in[3];   // (64, 128)
    const float* W2   = (const float*)d_in[4];   // (128, 512)
    const int*   src  = (const int*)d_in[5];     // (E,)
    const int*   dst  = (const int*)d_in[6];     // (E,)

    int E  = in_sizes[5];
    int nd = out_size / OUT_COLS;

    zero_kernel<<<(nd + 255) / 256, 256>>>(nd);
    hist_kernel<<<(E + 255) / 256, 256>>>(dst, E);
    scan_kernel<<<1, 1024>>>(nd);
    fill_kernel<<<(E + 255) / 256, 256>>>(dst, E);

    size_t smem = (size_t)SM_TOTAL * sizeof(float);   // 90624 B
    cudaFuncSetAttribute(mlp_kernel, cudaFuncAttributeMaxDynamicSharedMemorySize, (int)smem);
    mlp_kernel<<<(E + EPB - 1) / EPB, 256, smem>>>(emb, W1, W2, E);

    gather_kernel<<<nd, 128>>>(xsrc, sh, src, (float*)d_out);
}

// round 5
// speedup vs baseline: 2.4428x; 2.4428x over previous
#include <cuda_runtime.h>
#include <cuda_bf16.h>
#include <math.h>

// Problem constants (fixed by the dataset)
#define E_MAX   100000
#define ND_MAX  10000
#define C_DIM   128
#define MLP_IN  64
#define HID     128
#define WOUT    512      // 4 * 128
#define SH_DIM  16
#define OUT_COLS 2048    // 128 * (1+3+5+7)

// -------- device scratch (static allocation: allowed) --------
__device__ int   g_count [ND_MAX];
__device__ int   g_cursor[ND_MAX];
__device__ int   g_offset[ND_MAX + 1];
__device__ int   g_elist [E_MAX];
__device__ float g_tpw   [(size_t)E_MAX * WOUT];          // 204.8 MB edge MLP output
// W2 pre-scaled, split to bf16 hi/lo, packed as k-pairs: [64 kpairs][512 n] uint32
__device__ unsigned int g_W2hp[64 * WOUT];
__device__ unsigned int g_W2lp[64 * WOUT];

// ==================== CSR build ====================

__global__ void zero_kernel(int nd) {
    int i = blockIdx.x * blockDim.x + threadIdx.x;
    if (i < nd) { g_count[i] = 0; g_cursor[i] = 0; }
}

__global__ void hist_kernel(const int* __restrict__ dst, int E) {
    int e = blockIdx.x * blockDim.x + threadIdx.x;
    if (e < E) atomicAdd(&g_count[dst[e]], 1);
}

__global__ void scan_kernel(int nd) {
    __shared__ int s[1024];
    int t = threadIdx.x;
    int chunk = (nd + 1023) / 1024;
    int beg = t * chunk;
    int end = min(beg + chunk, nd);
    int sum = 0;
    for (int i = beg; i < end; i++) sum += g_count[i];
    s[t] = sum;
    __syncthreads();
    for (int off = 1; off < 1024; off <<= 1) {
        int v = (t >= off) ? s[t - off] : 0;
        __syncthreads();
        s[t] += v;
        __syncthreads();
    }
    int run = s[t] - sum;
    for (int i = beg; i < end; i++) {
        g_offset[i] = run;
        run += g_count[i];
    }
    if (t == 1023) g_offset[nd] = s[1023];
}

__global__ void fill_kernel(const int* __restrict__ dst, int E) {
    int e = blockIdx.x * blockDim.x + threadIdx.x;
    if (e < E) {
        int d = dst[e];
        int p = atomicAdd(&g_cursor[d], 1);
        g_elist[g_offset[d] + p] = e;
    }
}

// ==================== W2 split/pack precompute ====================
// v = W2[k][n] / sqrt(128); hi = bf16(v); lo = bf16(v - hi).
// Packed layout: word[r*512 + n] = (bf16 at k=2r low16, k=2r+1 high16).

__global__ void w2pack_kernel(const float* __restrict__ W2) {
    int idx = blockIdx.x * blockDim.x + threadIdx.x;   // 64*512 = 32768
    if (idx >= 64 * WOUT) return;
    int r = idx >> 9, n = idx & 511;
    const float w2s = 0.08838834764831845f;
    float v0 = W2[(size_t)(2 * r)     * WOUT + n] * w2s;
    float v1 = W2[(size_t)(2 * r + 1) * WOUT + n] * w2s;
    __nv_bfloat16 h0 = __float2bfloat16_rn(v0);
    __nv_bfloat16 h1 = __float2bfloat16_rn(v1);
    __nv_bfloat16 l0 = __float2bfloat16_rn(v0 - __bfloat162float(h0));
    __nv_bfloat16 l1 = __float2bfloat16_rn(v1 - __bfloat162float(h1));
    __nv_bfloat162 hp; hp.x = h0; hp.y = h1;
    __nv_bfloat162 lp; lp.x = l0; lp.y = l1;
    g_W2hp[idx] = *(unsigned int*)&hp;
    g_W2lp[idx] = *(unsigned int*)&lp;
}

// ==================== fused edge MLP (bf16-split tensor cores) ====================
// 64 edges per block, 256 threads (8 warps).
// Phase B: H = silu(emb @ W1s) in fp32 FFMA, split to bf16 hi/lo in smem.
// Phase C: TPW = H @ W2s via mma.sync.m16n8k16 bf16, 3-pass split (AhBh+AhBl+AlBh).
//
// smem layout (bytes):
//   [0, 17408)          s_Hh  bf16 [64][136]   (row pad 136 -> conflict-free A frags)
//   [17408, 34816)      s_Hl  bf16 [64][136]
//   [34816, ...)        phase B: s_emb f32[64*64] (16KB) + s_W1 f32[64*128] (32KB)
//                       phase C: s_W2h u32[64][264] (67584B) + s_W2l u32[64][264]
// total = 34816 + 135168 = 169984 B

#define EPB 64
#define HSTR 136          // Hh/Hl row stride in bf16 elements
#define WCHS 264          // W2 chunk row stride in uint32 words
#define SMEM_BYTES (34816 + 2 * 64 * WCHS * 4)

__device__ __forceinline__ void mma_bf16(float* c, const unsigned* a, unsigned b0, unsigned b1) {
    asm volatile(
        "mma.sync.aligned.m16n8k16.row.col.f32.bf16.bf16.f32 "
        "{%0,%1,%2,%3}, {%4,%5,%6,%7}, {%8,%9}, {%0,%1,%2,%3};"
        : "+f"(c[0]), "+f"(c[1]), "+f"(c[2]), "+f"(c[3])
        : "r"(a[0]), "r"(a[1]), "r"(a[2]), "r"(a[3]), "r"(b0), "r"(b1));
}

__global__ __launch_bounds__(256, 1)
void mlp_kernel(const float* __restrict__ emb,
                const float* __restrict__ W1,
                int E) {
    extern __shared__ char smraw[];
    __nv_bfloat16* s_Hh = (__nv_bfloat16*)smraw;
    __nv_bfloat16* s_Hl = (__nv_bfloat16*)(smraw + 17408);
    char* base2 = smraw + 34816;

    int tid  = threadIdx.x;
    int lane = tid & 31;
    int w    = tid >> 5;
    int e0   = blockIdx.x * EPB;

    // ---------- phase A: load emb tile + W1 ----------
    {
        float* s_emb = (float*)base2;               // [64][64]
        float* s_W1  = (float*)(base2 + 16384);     // [64][128]
        for (int i = tid; i < EPB * MLP_IN; i += 256) {
            int e = i >> 6, k = i & 63;
            int ge = e0 + e;
            s_emb[i] = (ge < E) ? emb[(size_t)ge * MLP_IN + k] : 0.f;
        }
        for (int i = tid; i < MLP_IN * HID; i += 256)
            s_W1[i] = W1[i] * 0.125f;
        __syncthreads();

        // ---------- phase B: H = silu(emb @ W1s), register-blocked 4e x 8c ----------
        int eg = tid >> 4;              // 0..15 -> edges eg*4 .. +3
        int c0 = (tid & 15) * 8;        // 8 hid cols
        float acc[4][8];
#pragma unroll
        for (int i = 0; i < 4; i++)
#pragma unroll
            for (int j = 0; j < 8; j++) acc[i][j] = 0.f;

#pragma unroll 4
        for (int k = 0; k < MLP_IN; k++) {
            float a0 = s_emb[(eg * 4 + 0) * MLP_IN + k];
            float a1 = s_emb[(eg * 4 + 1) * MLP_IN + k];
            float a2 = s_emb[(eg * 4 + 2) * MLP_IN + k];
            float a3 = s_emb[(eg * 4 + 3) * MLP_IN + k];
            float4 w0 = *(const float4*)&s_W1[k * HID + c0];
            float4 w1 = *(const float4*)&s_W1[k * HID + c0 + 4];
            float wv[8] = {w0.x, w0.y, w0.z, w0.w, w1.x, w1.y, w1.z, w1.w};
#pragma unroll
            for (int j = 0; j < 8; j++) {
                acc[0][j] += a0 * wv[j];
                acc[1][j] += a1 * wv[j];
                acc[2][j] += a2 * wv[j];
                acc[3][j] += a3 * wv[j];
            }
        }
        // silu + bf16 split -> smem
#pragma unroll
        for (int i = 0; i < 4; i++) {
            int e = eg * 4 + i;
#pragma unroll
            for (int j = 0; j < 8; j++) {
                float v  = acc[i][j];
                float sg = 1.f / (1.f + __expf(-v));
                float hv = v * sg;
                __nv_bfloat16 hh = __float2bfloat16_rn(hv);
                __nv_bfloat16 hl = __float2bfloat16_rn(hv - __bfloat162float(hh));
                s_Hh[e * HSTR + c0 + j] = hh;
                s_Hl[e * HSTR + c0 + j] = hl;
            }
        }
    }

    // ---------- phase C: TPW = H @ W2s via mma ----------
    unsigned* s_W2h = (unsigned*)base2;                       // [64][WCHS]
    unsigned* s_W2l = (unsigned*)(base2 + 64 * WCHS * 4);
    const unsigned* Hh32 = (const unsigned*)s_Hh;
    const unsigned* Hl32 = (const unsigned*)s_Hl;

    int q  = lane >> 2;     // groupID 0..7
    int tg = lane & 3;      // 0..3

    for (int nb = 0; nb < 2; nb++) {
        __syncthreads();    // previous chunk fully consumed (or phase B done)
        // load W2 chunk (256 n cols), uint4 vectorized, into padded-stride smem
        {
            const uint4* gh = (const uint4*)(g_W2hp + nb * 256);
            const uint4* gl = (const uint4*)(g_W2lp + nb * 256);
            // per split: 64 rows x 64 uint4
            for (int i = tid; i < 64 * 64; i += 256) {
                int r = i >> 6, n4 = i & 63;
                ((uint4*)(s_W2h + r * WCHS))[n4] = gh[r * (WOUT / 4) + n4];
                ((uint4*)(s_W2l + r * WCHS))[n4] = gl[r * (WOUT / 4) + n4];
            }
        }
        __syncthreads();

        float acc[4][4][4];
#pragma unroll
        for (int mt = 0; mt < 4; mt++)
#pragma unroll
            for (int nt = 0; nt < 4; nt++)
#pragma unroll
                for (int r = 0; r < 4; r++) acc[mt][nt][r] = 0.f;

#pragma unroll
        for (int kt = 0; kt < 8; kt++) {
            // A fragments for all 4 m-tiles (hi and lo)
            unsigned ah[4][4], al[4][4];
#pragma unroll
            for (int mt = 0; mt < 4; mt++) {
                int rowA = mt * 16 + q;
                int i0 = rowA * (HSTR / 2) + kt * 8 + tg;   // uint32 index, HSTR/2=68
                ah[mt][0] = Hh32[i0];
                ah[mt][1] = Hh32[i0 + 8 * 68];
                ah[mt][2] = Hh32[i0 + 4];
                ah[mt][3] = Hh32[i0 + 8 * 68 + 4];
                al[mt][0] = Hl32[i0];
                al[mt][1] = Hl32[i0 + 8 * 68];
                al[mt][2] = Hl32[i0 + 4];
                al[mt][3] = Hl32[i0 + 8 * 68 + 4];
            }
            int r0 = kt * 8 + tg;
#pragma unroll
            for (int nt = 0; nt < 4; nt++) {
                int ncol = (w * 4 + nt) * 8 + q;
                unsigned bh0 = s_W2h[r0 * WCHS + ncol];
                unsigned bh1 = s_W2h[(r0 + 4) * WCHS + ncol];
                unsigned bl0 = s_W2l[r0 * WCHS + ncol];
                unsigned bl1 = s_W2l[(r0 + 4) * WCHS + ncol];
#pragma unroll
                for (int mt = 0; mt < 4; mt++) {
                    mma_bf16(acc[mt][nt], ah[mt], bh0, bh1);
                    mma_bf16(acc[mt][nt], ah[mt], bl0, bl1);
                    mma_bf16(acc[mt][nt], al[mt], bh0, bh1);
                }
            }
        }

        // epilogue: write fp32 to g_tpw
#pragma unroll
        for (int nt = 0; nt < 4; nt++) {
            int col0 = nb * 256 + (w * 4 + nt) * 8 + tg * 2;
#pragma unroll
            for (int mt = 0; mt < 4; mt++) {
                int row0 = e0 + mt * 16 + q;
                if (row0 < E)
                    *(float2*)&g_tpw[(size_t)row0 * WOUT + col0] =
                        make_float2(acc[mt][nt][0], acc[mt][nt][1]);
                int row1 = row0 + 8;
                if (row1 < E)
                    *(float2*)&g_tpw[(size_t)row1 * WOUT + col0] =
                        make_float2(acc[mt][nt][2], acc[mt][nt][3]);
            }
        }
    }
}

// ==================== per-dst gather (no float atomics) ====================

__global__ __launch_bounds__(128)
void gather_kernel(const float* __restrict__ xsrc,
                   const float* __restrict__ sh,
                   const int*   __restrict__ src,
                   float*       __restrict__ out) {
    int d = blockIdx.x;
    int c = threadIdx.x;   // 0..127
    __shared__ float s_sh[SH_DIM];
    __shared__ float s_out[OUT_COLS];

    float acc[16];
#pragma unroll
    for (int i = 0; i < 16; i++) acc[i] = 0.f;

    int beg = g_offset[d], end = g_offset[d + 1];
    for (int k = beg; k < end; k++) {
        int e = g_elist[k];
        __syncthreads();
        if (c < SH_DIM) s_sh[c] = sh[(size_t)e * SH_DIM + c];
        __syncthreads();
        int s = src[e];
        float xs = xsrc[(size_t)s * C_DIM + c];
        const float* tp = &g_tpw[(size_t)e * WOUT];
        float t0 = tp[c]       * xs;
        float t1 = tp[128 + c] * xs;
        float t2 = tp[256 + c] * xs;
        float t3 = tp[384 + c] * xs;
        acc[0] += t0 * s_sh[0];
#pragma unroll
        for (int m = 0; m < 3; m++) acc[1 + m] += t1 * s_sh[1 + m];
#pragma unroll
        for (int m = 0; m < 5; m++) acc[4 + m] += t2 * s_sh[4 + m];
#pragma unroll
        for (int m = 0; m < 7; m++) acc[9 + m] += t3 * s_sh[9 + m];
    }

    s_out[c] = acc[0];
#pragma unroll
    for (int m = 0; m < 3; m++) s_out[128  + c * 3 + m] = acc[1 + m];
#pragma unroll
    for (int m = 0; m < 5; m++) s_out[512  + c * 5 + m] = acc[4 + m];
#pragma unroll
    for (int m = 0; m < 7; m++) s_out[1152 + c * 7 + m] = acc[9 + m];
    __syncthreads();

    float4* o4 = (float4*)(out + (size_t)d * OUT_COLS);
    const float4* s4 = (const float4*)s_out;
    for (int i = c; i < OUT_COLS / 4; i += 128) o4[i] = s4[i];
}

// ==================== launch ====================

extern "C" void kernel_launch(void* const* d_in, const int* in_sizes, int n_in,
                              void* d_out, int out_size) {
    const float* xsrc = (const float*)d_in[0];
    const float* sh   = (const float*)d_in[1];
    const float* emb  = (const float*)d_in[2];
    const float* W1   = (const float*)d_in[3];
    const float* W2   = (const float*)d_in[4];
    const int*   src  = (const int*)d_in[5];
    const int*   dst  = (const int*)d_in[6];

    int E  = in_sizes[5];
    int nd = out_size / OUT_COLS;

    zero_kernel<<<(nd + 255) / 256, 256>>>(nd);
    hist_kernel<<<(E + 255) / 256, 256>>>(dst, E);
    scan_kernel<<<1, 1024>>>(nd);
    fill_kernel<<<(E + 255) / 256, 256>>>(dst, E);
    w2pack_kernel<<<(64 * WOUT + 255) / 256, 256>>>(W2);

    cudaFuncSetAttribute(mlp_kernel, cudaFuncAttributeMaxDynamicSharedMemorySize, SMEM_BYTES);
    mlp_kernel<<<(E + EPB - 1) / EPB, 256, SMEM_BYTES>>>(emb, W1, E);

    gather_kernel<<<nd, 128>>>(xsrc, sh, src, (float*)d_out);
}

// round 7
// speedup vs baseline: 3.3758x; 1.3820x over previous
#include <cuda_runtime.h>
#include <cuda_bf16.h>
#include <math.h>

// Problem constants (fixed by the dataset)
#define E_MAX   100000
#define ND_MAX  10000
#define C_DIM   128
#define MLP_IN  64
#define HID     128
#define WOUT    512      // 4 * 128
#define SH_DIM  16
#define OUT_COLS 2048    // 128 * (1+3+5+7)

// -------- device scratch (static allocation: allowed) --------
__device__ int   g_count [ND_MAX];
__device__ int   g_cursor[ND_MAX];
__device__ int   g_offset[ND_MAX + 1];
__device__ int   g_elist [E_MAX];
__device__ float g_tpw   [(size_t)E_MAX * WOUT];          // 204.8 MB edge MLP output
// W2 pre-scaled, split to bf16 hi/lo, packed as k-pairs: [64 kpairs][512 n] uint32
__device__ unsigned int g_W2hp[64 * WOUT];
__device__ unsigned int g_W2lp[64 * WOUT];

// ==================== CSR build ====================

__global__ void zero_kernel(int nd) {
    int i = blockIdx.x * blockDim.x + threadIdx.x;
    if (i < nd) { g_count[i] = 0; g_cursor[i] = 0; }
}

__global__ void hist_kernel(const int* __restrict__ dst, int E) {
    int e = blockIdx.x * blockDim.x + threadIdx.x;
    if (e < E) atomicAdd(&g_count[dst[e]], 1);
}

__global__ void scan_kernel(int nd) {
    __shared__ int s[1024];
    int t = threadIdx.x;
    int chunk = (nd + 1023) / 1024;
    int beg = t * chunk;
    int end = min(beg + chunk, nd);
    int sum = 0;
    for (int i = beg; i < end; i++) sum += g_count[i];
    s[t] = sum;
    __syncthreads();
    for (int off = 1; off < 1024; off <<= 1) {
        int v = (t >= off) ? s[t - off] : 0;
        __syncthreads();
        s[t] += v;
        __syncthreads();
    }
    int run = s[t] - sum;
    for (int i = beg; i < end; i++) {
        g_offset[i] = run;
        run += g_count[i];
    }
    if (t == 1023) g_offset[nd] = s[1023];
}

__global__ void fill_kernel(const int* __restrict__ dst, int E) {
    int e = blockIdx.x * blockDim.x + threadIdx.x;
    if (e < E) {
        int d = dst[e];
        int p = atomicAdd(&g_cursor[d], 1);
        g_elist[g_offset[d] + p] = e;
    }
}

// ==================== W2 split/pack precompute ====================

__global__ void w2pack_kernel(const float* __restrict__ W2) {
    int idx = blockIdx.x * blockDim.x + threadIdx.x;   // 64*512 = 32768
    if (idx >= 64 * WOUT) return;
    int r = idx >> 9, n = idx & 511;
    const float w2s = 0.08838834764831845f;
    float v0 = W2[(size_t)(2 * r)     * WOUT + n] * w2s;
    float v1 = W2[(size_t)(2 * r + 1) * WOUT + n] * w2s;
    __nv_bfloat16 h0 = __float2bfloat16_rn(v0);
    __nv_bfloat16 h1 = __float2bfloat16_rn(v1);
    __nv_bfloat16 l0 = __float2bfloat16_rn(v0 - __bfloat162float(h0));
    __nv_bfloat16 l1 = __float2bfloat16_rn(v1 - __bfloat162float(h1));
    __nv_bfloat162 hp; hp.x = h0; hp.y = h1;
    __nv_bfloat162 lp; lp.x = l0; lp.y = l1;
    g_W2hp[idx] = *(unsigned int*)&hp;
    g_W2lp[idx] = *(unsigned int*)&lp;
}

// ==================== fused edge MLP (bf16-split tensor cores) ====================
// 64 edges per block, 256 threads (8 warps), 2 blocks/SM (smem = 104448 B).
// Phase B: H = silu(emb @ W1s) fp32 FFMA -> bf16 hi/lo split in smem.
// Phase C: TPW = H @ W2s via mma.sync m16n8k16 bf16, 3-pass split, 4 n-chunks of 128.

#define EPB 64
#define HSTR 136          // Hh/Hl row stride in bf16 elements
#define WCHS 136          // W2 chunk row stride in uint32 words (128 + 8 pad)
#define SMEM_BYTES (34816 + 2 * 64 * WCHS * 4)   // 104448

__device__ __forceinline__ void mma_bf16(float* c, const unsigned* a, unsigned b0, unsigned b1) {
    asm volatile(
        "mma.sync.aligned.m16n8k16.row.col.f32.bf16.bf16.f32 "
        "{%0,%1,%2,%3}, {%4,%5,%6,%7}, {%8,%9}, {%0,%1,%2,%3};"
        : "+f"(c[0]), "+f"(c[1]), "+f"(c[2]), "+f"(c[3])
        : "r"(a[0]), "r"(a[1]), "r"(a[2]), "r"(a[3]), "r"(b0), "r"(b1));
}

__global__ __launch_bounds__(256, 2)
void mlp_kernel(const float* __restrict__ emb,
                const float* __restrict__ W1,
                int E) {
    extern __shared__ char smraw[];
    __nv_bfloat16* s_Hh = (__nv_bfloat16*)smraw;
    __nv_bfloat16* s_Hl = (__nv_bfloat16*)(smraw + 17408);
    char* base2 = smraw + 34816;

    int tid  = threadIdx.x;
    int lane = tid & 31;
    int w    = tid >> 5;
    int e0   = blockIdx.x * EPB;

    // ---------- phase A/B: emb tile + W1, H = silu(emb @ W1s) ----------
    {
        float* s_emb = (float*)base2;               // [64][64]
        float* s_W1  = (float*)(base2 + 16384);     // [64][128]
        for (int i = tid; i < EPB * MLP_IN; i += 256) {
            int e = i >> 6, k = i & 63;
            int ge = e0 + e;
            s_emb[i] = (ge < E) ? emb[(size_t)ge * MLP_IN + k] : 0.f;
        }
        for (int i = tid; i < MLP_IN * HID; i += 256)
            s_W1[i] = W1[i] * 0.125f;
        __syncthreads();

        int eg = tid >> 4;              // 0..15 -> edges eg*4 .. +3
        int c0 = (tid & 15) * 8;        // 8 hid cols
        float acc[4][8];
#pragma unroll
        for (int i = 0; i < 4; i++)
#pragma unroll
            for (int j = 0; j < 8; j++) acc[i][j] = 0.f;

#pragma unroll 4
        for (int k = 0; k < MLP_IN; k++) {
            float a0 = s_emb[(eg * 4 + 0) * MLP_IN + k];
            float a1 = s_emb[(eg * 4 + 1) * MLP_IN + k];
            float a2 = s_emb[(eg * 4 + 2) * MLP_IN + k];
            float a3 = s_emb[(eg * 4 + 3) * MLP_IN + k];
            float4 w0 = *(const float4*)&s_W1[k * HID + c0];
            float4 w1 = *(const float4*)&s_W1[k * HID + c0 + 4];
            float wv[8] = {w0.x, w0.y, w0.z, w0.w, w1.x, w1.y, w1.z, w1.w};
#pragma unroll
            for (int j = 0; j < 8; j++) {
                acc[0][j] += a0 * wv[j];
                acc[1][j] += a1 * wv[j];
                acc[2][j] += a2 * wv[j];
                acc[3][j] += a3 * wv[j];
            }
        }
#pragma unroll
        for (int i = 0; i < 4; i++) {
            int e = eg * 4 + i;
#pragma unroll
            for (int j = 0; j < 8; j++) {
                float v  = acc[i][j];
                float sg = 1.f / (1.f + __expf(-v));
                float hv = v * sg;
                __nv_bfloat16 hh = __float2bfloat16_rn(hv);
                __nv_bfloat16 hl = __float2bfloat16_rn(hv - __bfloat162float(hh));
                s_Hh[e * HSTR + c0 + j] = hh;
                s_Hl[e * HSTR + c0 + j] = hl;
            }
        }
    }

    // ---------- phase C: TPW = H @ W2s via mma, 4 chunks of 128 n-cols ----------
    unsigned* s_W2h = (unsigned*)base2;                       // [64][WCHS]
    unsigned* s_W2l = (unsigned*)(base2 + 64 * WCHS * 4);
    const unsigned* Hh32 = (const unsigned*)s_Hh;
    const unsigned* Hl32 = (const unsigned*)s_Hl;

    int q  = lane >> 2;     // groupID 0..7
    int tg = lane & 3;      // 0..3

    for (int nb = 0; nb < 4; nb++) {
        __syncthreads();    // previous chunk fully consumed (or phase B done)
        {
            const uint4* gh = ((const uint4*)g_W2hp) + nb * 32;
            const uint4* gl = ((const uint4*)g_W2lp) + nb * 32;
            // per split: 64 rows x 32 uint4
            for (int i = tid; i < 64 * 32; i += 256) {
                int r = i >> 5, n4 = i & 31;
                ((uint4*)(s_W2h + r * WCHS))[n4] = gh[r * 128 + n4];
                ((uint4*)(s_W2l + r * WCHS))[n4] = gl[r * 128 + n4];
            }
        }
        __syncthreads();

        float acc[4][2][4];
#pragma unroll
        for (int mt = 0; mt < 4; mt++)
#pragma unroll
            for (int nt = 0; nt < 2; nt++)
#pragma unroll
                for (int r = 0; r < 4; r++) acc[mt][nt][r] = 0.f;

#pragma unroll
        for (int kt = 0; kt < 8; kt++) {
            // A fragments for all 4 m-tiles (hi and lo)
            unsigned ah[4][4], al[4][4];
#pragma unroll
            for (int mt = 0; mt < 4; mt++) {
                int rowA = mt * 16 + q;
                int i0 = rowA * (HSTR / 2) + kt * 8 + tg;   // uint32 index, HSTR/2=68
                ah[mt][0] = Hh32[i0];
                ah[mt][1] = Hh32[i0 + 8 * 68];
                ah[mt][2] = Hh32[i0 + 4];
                ah[mt][3] = Hh32[i0 + 8 * 68 + 4];
                al[mt][0] = Hl32[i0];
                al[mt][1] = Hl32[i0 + 8 * 68];
                al[mt][2] = Hl32[i0 + 4];
                al[mt][3] = Hl32[i0 + 8 * 68 + 4];
            }
            // B fragments for both n-tiles
            int r0 = kt * 8 + tg;
            unsigned bh[2][2], bl[2][2];
#pragma unroll
            for (int nt = 0; nt < 2; nt++) {
                int ncol = w * 16 + nt * 8 + q;
                bh[nt][0] = s_W2h[r0 * WCHS + ncol];
                bh[nt][1] = s_W2h[(r0 + 4) * WCHS + ncol];
                bl[nt][0] = s_W2l[r0 * WCHS + ncol];
                bl[nt][1] = s_W2l[(r0 + 4) * WCHS + ncol];
            }
            // pass-major issue: same-acc reuse distance = 8 MMAs
#pragma unroll
            for (int mt = 0; mt < 4; mt++)
#pragma unroll
                for (int nt = 0; nt < 2; nt++)
                    mma_bf16(acc[mt][nt], ah[mt], bh[nt][0], bh[nt][1]);
#pragma unroll
            for (int mt = 0; mt < 4; mt++)
#pragma unroll
                for (int nt = 0; nt < 2; nt++)
                    mma_bf16(acc[mt][nt], ah[mt], bl[nt][0], bl[nt][1]);
#pragma unroll
            for (int mt = 0; mt < 4; mt++)
#pragma unroll
                for (int nt = 0; nt < 2; nt++)
                    mma_bf16(acc[mt][nt], al[mt], bh[nt][0], bh[nt][1]);
        }

        // epilogue: write fp32 to g_tpw
#pragma unroll
        for (int nt = 0; nt < 2; nt++) {
            int col0 = nb * 128 + (w * 2 + nt) * 8 + tg * 2;
#pragma unroll
            for (int mt = 0; mt < 4; mt++) {
                int row0 = e0 + mt * 16 + q;
                if (row0 < E)
                    *(float2*)&g_tpw[(size_t)row0 * WOUT + col0] =
                        make_float2(acc[mt][nt][0], acc[mt][nt][1]);
                int row1 = row0 + 8;
                if (row1 < E)
                    *(float2*)&g_tpw[(size_t)row1 * WOUT + col0] =
                        make_float2(acc[mt][nt][2], acc[mt][nt][3]);
            }
        }
    }
}

// ==================== per-dst gather (sync-light, edge-chunked) ====================
// Block = one dst node, 128 threads (thread = channel c).
// Edge metadata (e, src, sh-row) staged into smem per 32-edge chunk, so the
// inner loop has NO barriers and NO dependent index chains -> unroll-4 MLP.

__global__ __launch_bounds__(128)
void gather_kernel(const float* __restrict__ xsrc,
                   const float* __restrict__ sh,
                   const int*   __restrict__ src,
                   float*       __restrict__ out) {
    int d = blockIdx.x;
    int c = threadIdx.x;   // 0..127
    __shared__ int   s_e[32];
    __shared__ int   s_s[32];
    __shared__ float s_shv[32 * SH_DIM];
    __shared__ float s_out[OUT_COLS];

    float acc[16];
#pragma unroll
    for (int i = 0; i < 16; i++) acc[i] = 0.f;

    int beg = g_offset[d], end = g_offset[d + 1];

    for (int base = beg; base < end; base += 32) {
        int cnt = min(32, end - base);
        __syncthreads();
        if (c < cnt) s_e[c] = g_elist[base + c];
        __syncthreads();
        if (c < cnt) s_s[c] = src[s_e[c]];
        for (int idx = c; idx < cnt * SH_DIM; idx += 128)
            s_shv[idx] = sh[(size_t)s_e[idx >> 4] * SH_DIM + (idx & 15)];
        __syncthreads();

#pragma unroll 4
        for (int j = 0; j < cnt; j++) {
            int e = s_e[j];
            int s = s_s[j];
            float xs = xsrc[(size_t)s * C_DIM + c];
            const float* tp = &g_tpw[(size_t)e * WOUT];
            float t0 = tp[c]       * xs;
            float t1 = tp[128 + c] * xs;
            float t2 = tp[256 + c] * xs;
            float t3 = tp[384 + c] * xs;
            const float* sv = &s_shv[j * SH_DIM];
            acc[0] += t0 * sv[0];
#pragma unroll
            for (int m = 0; m < 3; m++) acc[1 + m] += t1 * sv[1 + m];
#pragma unroll
            for (int m = 0; m < 5; m++) acc[4 + m] += t2 * sv[4 + m];
#pragma unroll
            for (int m = 0; m < 7; m++) acc[9 + m] += t3 * sv[9 + m];
        }
    }

    // stage to smem in final layout (concat over l, inner index c*d+m)
    __syncthreads();
    s_out[c] = acc[0];
#pragma unroll
    for (int m = 0; m < 3; m++) s_out[128  + c * 3 + m] = acc[1 + m];
#pragma unroll
    for (int m = 0; m < 5; m++) s_out[512  + c * 5 + m] = acc[4 + m];
#pragma unroll
    for (int m = 0; m < 7; m++) s_out[1152 + c * 7 + m] = acc[9 + m];
    __syncthreads();

    float4* o4 = (float4*)(out + (size_t)d * OUT_COLS);
    const float4* s4 = (const float4*)s_out;
    for (int i = c; i < OUT_COLS / 4; i += 128) o4[i] = s4[i];
}

// ==================== launch ====================

extern "C" void kernel_launch(void* const* d_in, const int* in_sizes, int n_in,
                              void* d_out, int out_size) {
    const float* xsrc = (const float*)d_in[0];
    const float* sh   = (const float*)d_in[1];
    const float* emb  = (const float*)d_in[2];
    const float* W1   = (const float*)d_in[3];
    const float* W2   = (const float*)d_in[4];
    const int*   src  = (const int*)d_in[5];
    const int*   dst  = (const int*)d_in[6];

    int E  = in_sizes[5];
    int nd = out_size / OUT_COLS;

    zero_kernel<<<(nd + 255) / 256, 256>>>(nd);
    hist_kernel<<<(E + 255) / 256, 256>>>(dst, E);
    scan_kernel<<<1, 1024>>>(nd);
    fill_kernel<<<(E + 255) / 256, 256>>>(dst, E);
    w2pack_kernel<<<(64 * WOUT + 255) / 256, 256>>>(W2);

    cudaFuncSetAttribute(mlp_kernel, cudaFuncAttributeMaxDynamicSharedMemorySize, SMEM_BYTES);
    mlp_kernel<<<(E + EPB - 1) / EPB, 256, SMEM_BYTES>>>(emb, W1, E);

    gather_kernel<<<nd, 128>>>(xsrc, sh, src, (float*)d_out);
}

// round 9
// speedup vs baseline: 4.0872x; 1.2107x over previous
#include <cuda_runtime.h>
#include <cuda_fp16.h>
#include <cuda_bf16.h>
#include <math.h>

// Problem constants (fixed by the dataset)
#define E_MAX   100000
#define ND_MAX  10000
#define C_DIM   128
#define MLP_IN  64
#define HID     128
#define WOUT    512      // 4 * 128
#define SH_DIM  16
#define OUT_COLS 2048    // 128 * (1+3+5+7)

// -------- device scratch (static allocation: allowed) --------
__device__ int    g_count [ND_MAX];
__device__ int    g_cursor[ND_MAX];
__device__ int    g_offset[ND_MAX + 1];
__device__ int    g_elist [E_MAX];
__device__ __half g_tpwh  [(size_t)E_MAX * WOUT];   // 102.4 MB edge MLP output (fp16)
// W2 pre-scaled fp16, packed as k-pairs: word[r*512+n] = (k=2r, k=2r+1)
__device__ unsigned int g_W2p[64 * WOUT];

// ==================== CSR build ====================

__global__ void zero_kernel(int nd) {
    int i = blockIdx.x * blockDim.x + threadIdx.x;
    if (i < nd) { g_count[i] = 0; g_cursor[i] = 0; }
}

__global__ void hist_kernel(const int* __restrict__ dst, int E) {
    int e = blockIdx.x * blockDim.x + threadIdx.x;
    if (e < E) atomicAdd(&g_count[dst[e]], 1);
}

__global__ void scan_kernel(int nd) {
    __shared__ int s[1024];
    int t = threadIdx.x;
    int chunk = (nd + 1023) / 1024;
    int beg = t * chunk;
    int end = min(beg + chunk, nd);
    int sum = 0;
    for (int i = beg; i < end; i++) sum += g_count[i];
    s[t] = sum;
    __syncthreads();
    for (int off = 1; off < 1024; off <<= 1) {
        int v = (t >= off) ? s[t - off] : 0;
        __syncthreads();
        s[t] += v;
        __syncthreads();
    }
    int run = s[t] - sum;
    for (int i = beg; i < end; i++) {
        g_offset[i] = run;
        run += g_count[i];
    }
    if (t == 1023) g_offset[nd] = s[1023];
}

__global__ void fill_kernel(const int* __restrict__ dst, int E) {
    int e = blockIdx.x * blockDim.x + threadIdx.x;
    if (e < E) {
        int d = dst[e];
        int p = atomicAdd(&g_cursor[d], 1);
        g_elist[g_offset[d] + p] = e;
    }
}

// ==================== W2 fp16 pack precompute ====================

__global__ void w2pack_kernel(const float* __restrict__ W2) {
    int idx = blockIdx.x * blockDim.x + threadIdx.x;   // 64*512 = 32768
    if (idx >= 64 * WOUT) return;
    int r = idx >> 9, n = idx & 511;
    const float w2s = 0.08838834764831845f;            // 1/sqrt(128)
    float v0 = W2[(size_t)(2 * r)     * WOUT + n] * w2s;
    float v1 = W2[(size_t)(2 * r + 1) * WOUT + n] * w2s;
    __half2 hp = __floats2half2_rn(v0, v1);
    g_W2p[idx] = *(unsigned int*)&hp;
}

// ==================== fused edge MLP (fp16 tensor cores) ====================
// 64 edges per block, 256 threads (8 warps), 2 blocks/SM.
// Phase B: H = silu(emb @ W1s) fp32 FFMA -> fp16 in smem.
// Phase C: TPW = H @ W2s via mma.sync m16n8k16 fp16 (single pass), 2 n-chunks of 256.
//
// smem layout (bytes):
//   [0, 17408)   s_H fp16 [64][136]  (row pad -> conflict-free A frags)
//   [17408, ...) phase B: s_emb f32[64*64] (16KB) + s_W1 f32[64*128] (32KB)
//                phase C: s_W2 u32 [64][264]  (67584 B)
// total = 17408 + 67584 = 84992 B

#define EPB 64
#define HSTR 136          // H row stride in halves (68 u32)
#define WCHS 264          // W2 chunk row stride in u32 (256 + 8 pad)
#define SMEM_BYTES (17408 + 64 * WCHS * 4)   // 84992

__device__ __forceinline__ void mma_fp16(float* c, const unsigned* a, unsigned b0, unsigned b1) {
    asm volatile(
        "mma.sync.aligned.m16n8k16.row.col.f32.f16.f16.f32 "
        "{%0,%1,%2,%3}, {%4,%5,%6,%7}, {%8,%9}, {%0,%1,%2,%3};"
        : "+f"(c[0]), "+f"(c[1]), "+f"(c[2]), "+f"(c[3])
        : "r"(a[0]), "r"(a[1]), "r"(a[2]), "r"(a[3]), "r"(b0), "r"(b1));
}

__global__ __launch_bounds__(256, 2)
void mlp_kernel(const float* __restrict__ emb,
                const float* __restrict__ W1,
                int E) {
    extern __shared__ char smraw[];
    __half* s_H = (__half*)smraw;
    char* base2 = smraw + 17408;

    int tid  = threadIdx.x;
    int lane = tid & 31;
    int w    = tid >> 5;
    int e0   = blockIdx.x * EPB;

    // ---------- phase A/B: emb tile + W1, H = silu(emb @ W1s) ----------
    {
        float* s_emb = (float*)base2;               // [64][64]
        float* s_W1  = (float*)(base2 + 16384);     // [64][128]
        for (int i = tid; i < EPB * MLP_IN; i += 256) {
            int e = i >> 6, k = i & 63;
            int ge = e0 + e;
            s_emb[i] = (ge < E) ? emb[(size_t)ge * MLP_IN + k] : 0.f;
        }
        for (int i = tid; i < MLP_IN * HID; i += 256)
            s_W1[i] = W1[i] * 0.125f;
        __syncthreads();

        int eg = tid >> 4;              // 0..15 -> edges eg*4 .. +3
        int c0 = (tid & 15) * 8;        // 8 hid cols
        float acc[4][8];
#pragma unroll
        for (int i = 0; i < 4; i++)
#pragma unroll
            for (int j = 0; j < 8; j++) acc[i][j] = 0.f;

#pragma unroll 4
        for (int k = 0; k < MLP_IN; k++) {
            float a0 = s_emb[(eg * 4 + 0) * MLP_IN + k];
            float a1 = s_emb[(eg * 4 + 1) * MLP_IN + k];
            float a2 = s_emb[(eg * 4 + 2) * MLP_IN + k];
            float a3 = s_emb[(eg * 4 + 3) * MLP_IN + k];
            float4 w0 = *(const float4*)&s_W1[k * HID + c0];
            float4 w1 = *(const float4*)&s_W1[k * HID + c0 + 4];
            float wv[8] = {w0.x, w0.y, w0.z, w0.w, w1.x, w1.y, w1.z, w1.w};
#pragma unroll
            for (int j = 0; j < 8; j++) {
                acc[0][j] += a0 * wv[j];
                acc[1][j] += a1 * wv[j];
                acc[2][j] += a2 * wv[j];
                acc[3][j] += a3 * wv[j];
            }
        }
#pragma unroll
        for (int i = 0; i < 4; i++) {
            int e = eg * 4 + i;
#pragma unroll
            for (int j = 0; j < 8; j++) {
                float v  = acc[i][j];
                float sg = 1.f / (1.f + __expf(-v));
                s_H[e * HSTR + c0 + j] = __float2half_rn(v * sg);
            }
        }
    }

    // ---------- phase C: TPW = H @ W2s via fp16 mma, 2 chunks of 256 n-cols ----------
    unsigned* s_W2 = (unsigned*)base2;              // [64][WCHS]
    const unsigned* H32 = (const unsigned*)s_H;

    int q  = lane >> 2;     // groupID 0..7
    int tg = lane & 3;      // 0..3

    for (int nb = 0; nb < 2; nb++) {
        __syncthreads();    // phase B done / previous chunk consumed
        {
            const uint4* gp = ((const uint4*)g_W2p) + nb * 64;
            // 64 rows x 64 uint4 per chunk
            for (int i = tid; i < 64 * 64; i += 256) {
                int r = i >> 6, n4 = i & 63;
                ((uint4*)(s_W2 + r * WCHS))[n4] = gp[r * 128 + n4];
            }
        }
        __syncthreads();

        float acc[4][4][4];
#pragma unroll
        for (int mt = 0; mt < 4; mt++)
#pragma unroll
            for (int nt = 0; nt < 4; nt++)
#pragma unroll
                for (int r = 0; r < 4; r++) acc[mt][nt][r] = 0.f;

#pragma unroll
        for (int kt = 0; kt < 8; kt++) {
            // A fragments for all 4 m-tiles
            unsigned a[4][4];
#pragma unroll
            for (int mt = 0; mt < 4; mt++) {
                int rowA = mt * 16 + q;
                int i0 = rowA * (HSTR / 2) + kt * 8 + tg;   // u32 index, HSTR/2=68
                a[mt][0] = H32[i0];
                a[mt][1] = H32[i0 + 8 * 68];
                a[mt][2] = H32[i0 + 4];
                a[mt][3] = H32[i0 + 8 * 68 + 4];
            }
            // B fragments for 4 n-tiles (warp covers 32 n-cols)
            int r0 = kt * 8 + tg;
            unsigned b[4][2];
#pragma unroll
            for (int nt = 0; nt < 4; nt++) {
                int ncol = w * 32 + nt * 8 + q;
                b[nt][0] = s_W2[r0 * WCHS + ncol];
                b[nt][1] = s_W2[(r0 + 4) * WCHS + ncol];
            }
#pragma unroll
            for (int mt = 0; mt < 4; mt++)
#pragma unroll
                for (int nt = 0; nt < 4; nt++)
                    mma_fp16(acc[mt][nt], a[mt], b[nt][0], b[nt][1]);
        }

        // epilogue: convert to fp16, write half2 to g_tpwh
#pragma unroll
        for (int nt = 0; nt < 4; nt++) {
            int col0 = nb * 256 + w * 32 + nt * 8 + tg * 2;   // even
#pragma unroll
            for (int mt = 0; mt < 4; mt++) {
                int row0 = e0 + mt * 16 + q;
                if (row0 < E) {
                    __half2 hv = __floats2half2_rn(acc[mt][nt][0], acc[mt][nt][1]);
                    *(__half2*)&g_tpwh[(size_t)row0 * WOUT + col0] = hv;
                }
                int row1 = row0 + 8;
                if (row1 < E) {
                    __half2 hv = __floats2half2_rn(acc[mt][nt][2], acc[mt][nt][3]);
                    *(__half2*)&g_tpwh[(size_t)row1 * WOUT + col0] = hv;
                }
            }
        }
    }
}

// ==================== per-dst gather (sync-light, edge-chunked) ====================
// Block = one dst node, 128 threads (thread = channel c).
// Edge metadata (e, src, sh-row) staged into smem per 32-edge chunk -> inner
// loop has no barriers and no dependent index chains.

__global__ __launch_bounds__(128)
void gather_kernel(const float* __restrict__ xsrc,
                   const float* __restrict__ sh,
                   const int*   __restrict__ src,
                   float*       __restrict__ out) {
    int d = blockIdx.x;
    int c = threadIdx.x;   // 0..127
    __shared__ int   s_e[32];
    __shared__ int   s_s[32];
    __shared__ float s_shv[32 * SH_DIM];
    __shared__ float s_out[OUT_COLS];

    float acc[16];
#pragma unroll
    for (int i = 0; i < 16; i++) acc[i] = 0.f;

    int beg = g_offset[d], end = g_offset[d + 1];

    for (int base = beg; base < end; base += 32) {
        int cnt = min(32, end - base);
        __syncthreads();
        if (c < cnt) s_e[c] = g_elist[base + c];
        __syncthreads();
        if (c < cnt) s_s[c] = src[s_e[c]];
        for (int idx = c; idx < cnt * SH_DIM; idx += 128)
            s_shv[idx] = sh[(size_t)s_e[idx >> 4] * SH_DIM + (idx & 15)];
        __syncthreads();

#pragma unroll 4
        for (int j = 0; j < cnt; j++) {
            int e = s_e[j];
            int s = s_s[j];
            float xs = xsrc[(size_t)s * C_DIM + c];
            const __half* tp = &g_tpwh[(size_t)e * WOUT];
            float t0 = __half2float(tp[c])       * xs;
            float t1 = __half2float(tp[128 + c]) * xs;
            float t2 = __half2float(tp[256 + c]) * xs;
            float t3 = __half2float(tp[384 + c]) * xs;
            const float* sv = &s_shv[j * SH_DIM];
            acc[0] += t0 * sv[0];
#pragma unroll
            for (int m = 0; m < 3; m++) acc[1 + m] += t1 * sv[1 + m];
#pragma unroll
            for (int m = 0; m < 5; m++) acc[4 + m] += t2 * sv[4 + m];
#pragma unroll
            for (int m = 0; m < 7; m++) acc[9 + m] += t3 * sv[9 + m];
        }
    }

    // stage to smem in final layout (concat over l, inner index c*d+m)
    __syncthreads();
    s_out[c] = acc[0];
#pragma unroll
    for (int m = 0; m < 3; m++) s_out[128  + c * 3 + m] = acc[1 + m];
#pragma unroll
    for (int m = 0; m < 5; m++) s_out[512  + c * 5 + m] = acc[4 + m];
#pragma unroll
    for (int m = 0; m < 7; m++) s_out[1152 + c * 7 + m] = acc[9 + m];
    __syncthreads();

    float4* o4 = (float4*)(out + (size_t)d * OUT_COLS);
    const float4* s4 = (const float4*)s_out;
    for (int i = c; i < OUT_COLS / 4; i += 128) o4[i] = s4[i];
}

// ==================== launch ====================

extern "C" void kernel_launch(void* const* d_in, const int* in_sizes, int n_in,
                              void* d_out, int out_size) {
    const float* xsrc = (const float*)d_in[0];
    const float* sh   = (const float*)d_in[1];
    const float* emb  = (const float*)d_in[2];
    const float* W1   = (const float*)d_in[3];
    const float* W2   = (const float*)d_in[4];
    const int*   src  = (const int*)d_in[5];
    const int*   dst  = (const int*)d_in[6];

    int E  = in_sizes[5];
    int nd = out_size / OUT_COLS;

    zero_kernel<<<(nd + 255) / 256, 256>>>(nd);
    hist_kernel<<<(E + 255) / 256, 256>>>(dst, E);
    scan_kernel<<<1, 1024>>>(nd);
    fill_kernel<<<(E + 255) / 256, 256>>>(dst, E);
    w2pack_kernel<<<(64 * WOUT + 255) / 256, 256>>>(W2);

    cudaFuncSetAttribute(mlp_kernel, cudaFuncAttributeMaxDynamicSharedMemorySize, SMEM_BYTES);
    mlp_kernel<<<(E + EPB - 1) / EPB, 256, SMEM_BYTES>>>(emb, W1, E);

    gather_kernel<<<nd, 128>>>(xsrc, sh, src, (float*)d_out);
}

// round 11
// speedup vs baseline: 5.1044x; 1.2489x over previous
#include <cuda_runtime.h>
#include <cuda_fp16.h>
#include <math.h>

// Problem constants (fixed by the dataset)
#define E_MAX   100000
#define ND_MAX  10000
#define C_DIM   128
#define MLP_IN  64
#define HID     128
#define WOUT    512      // 4 * 128
#define SH_DIM  16
#define OUT_COLS 2048    // 128 * (1+3+5+7)

// -------- device scratch (static allocation: allowed) --------
__device__ int    g_count [ND_MAX];
__device__ int    g_cursor[ND_MAX];
__device__ int    g_offset[ND_MAX + 1];
__device__ int    g_elist [E_MAX];
__device__ __half g_tpwh  [(size_t)E_MAX * WOUT];   // 102.4 MB edge MLP output (fp16)
// Weights pre-scaled fp16, packed as k-pairs: word[r*N+n] = (k=2r, k=2r+1)
__device__ unsigned int g_W2p[64 * WOUT];   // [64 kpairs][512 n]
__device__ unsigned int g_W1p[32 * HID];    // [32 kpairs][128 n]

// ==================== CSR build ====================

__global__ void zero_kernel(int nd) {
    int i = blockIdx.x * blockDim.x + threadIdx.x;
    if (i < nd) { g_count[i] = 0; g_cursor[i] = 0; }
}

__global__ void hist_kernel(const int* __restrict__ dst, int E) {
    int e = blockIdx.x * blockDim.x + threadIdx.x;
    if (e < E) atomicAdd(&g_count[dst[e]], 1);
}

__global__ void scan_kernel(int nd) {
    __shared__ int s[1024];
    int t = threadIdx.x;
    int chunk = (nd + 1023) / 1024;
    int beg = t * chunk;
    int end = min(beg + chunk, nd);
    int sum = 0;
    for (int i = beg; i < end; i++) sum += g_count[i];
    s[t] = sum;
    __syncthreads();
    for (int off = 1; off < 1024; off <<= 1) {
        int v = (t >= off) ? s[t - off] : 0;
        __syncthreads();
        s[t] += v;
        __syncthreads();
    }
    int run = s[t] - sum;
    for (int i = beg; i < end; i++) {
        g_offset[i] = run;
        run += g_count[i];
    }
    if (t == 1023) g_offset[nd] = s[1023];
}

__global__ void fill_kernel(const int* __restrict__ dst, int E) {
    int e = blockIdx.x * blockDim.x + threadIdx.x;
    if (e < E) {
        int d = dst[e];
        int p = atomicAdd(&g_cursor[d], 1);
        g_elist[g_offset[d] + p] = e;
    }
}

// ==================== weight fp16 pack precompute (W1 + W2) ====================

__global__ void pack_kernel(const float* __restrict__ W1,
                            const float* __restrict__ W2) {
    int idx = blockIdx.x * blockDim.x + threadIdx.x;
    if (idx < 64 * WOUT) {                      // W2: 1/sqrt(128) scale
        int r = idx >> 9, n = idx & 511;
        const float w2s = 0.08838834764831845f;
        float v0 = W2[(size_t)(2 * r)     * WOUT + n] * w2s;
        float v1 = W2[(size_t)(2 * r + 1) * WOUT + n] * w2s;
        __half2 hp = __floats2half2_rn(v0, v1);
        g_W2p[idx] = *(unsigned int*)&hp;
    }
    if (idx < 32 * HID) {                       // W1: 1/8 scale
        int r = idx >> 7, n = idx & 127;
        float v0 = W1[(size_t)(2 * r)     * HID + n] * 0.125f;
        float v1 = W1[(size_t)(2 * r + 1) * HID + n] * 0.125f;
        __half2 hp = __floats2half2_rn(v0, v1);
        g_W1p[idx] = *(unsigned int*)&hp;
    }
}

// ==================== fused edge MLP (all-fp16 tensor cores) ====================
// 64 edges per block, 256 threads (8 warps), 2 blocks/SM.
// Phase B: H = silu(emb16 @ W1p) via fp16 mma (K=64).
// Phase C: TPW = H @ W2p via fp16 mma, 2 n-chunks of 256, smem-staged epilogue.
//
// smem (bytes):
//   [0, 17408)   s_H fp16 [64][HSTR=136]
//   [17408, ...) base2:
//     phase A/B: s_E fp16 [64][ESTR=72] (9216 B) + s_W1p u32 [32][136] (17408 B)
//     phase C:   s_W2 u32 [64][WCHS=264] (67584 B); epilogue reuses it as
//                fp16 [64][EPSTR=264] staging (33792 B)
// total = 17408 + 67584 = 84992 B

#define EPB 64
#define HSTR 136
#define ESTR 72
#define WCHS 264
#define EPSTR 264
#define SMEM_BYTES (17408 + 64 * WCHS * 4)   // 84992

__device__ __forceinline__ void mma_fp16(float* c, const unsigned* a, unsigned b0, unsigned b1) {
    asm volatile(
        "mma.sync.aligned.m16n8k16.row.col.f32.f16.f16.f32 "
        "{%0,%1,%2,%3}, {%4,%5,%6,%7}, {%8,%9}, {%0,%1,%2,%3};"
        : "+f"(c[0]), "+f"(c[1]), "+f"(c[2]), "+f"(c[3])
        : "r"(a[0]), "r"(a[1]), "r"(a[2]), "r"(a[3]), "r"(b0), "r"(b1));
}

__device__ __forceinline__ float silu_f(float v) {
    return v / (1.f + __expf(-v));
}

__global__ __launch_bounds__(256, 2)
void mlp_kernel(const float* __restrict__ emb, int E) {
    extern __shared__ char smraw[];
    __half* s_H = (__half*)smraw;
    char* base2 = smraw + 17408;

    int tid  = threadIdx.x;
    int lane = tid & 31;
    int w    = tid >> 5;
    int e0   = blockIdx.x * EPB;
    int q    = lane >> 2;    // groupID 0..7
    int tg   = lane & 3;     // 0..3

    // ---------- phase A: emb -> fp16 smem, W1p -> smem ----------
    {
        __half*   s_E   = (__half*)base2;                 // [64][ESTR]
        unsigned* s_W1p = (unsigned*)(base2 + 9216);      // [32][136]
        for (int i = tid; i < EPB * MLP_IN; i += 256) {
            int e = i >> 6, k = i & 63;
            int ge = e0 + e;
            float v = (ge < E) ? emb[(size_t)ge * MLP_IN + k] : 0.f;
            s_E[e * ESTR + k] = __float2half_rn(v);
        }
        for (int i = tid; i < 32 * 32; i += 256) {        // 32 rows x 32 uint4
            int r = i >> 5, n4 = i & 31;
            ((uint4*)(s_W1p + r * 136))[n4] = ((const uint4*)g_W1p)[r * 32 + n4];
        }
        __syncthreads();

        // ---------- phase B: H = silu(E @ W1p), warp -> (mt, n-half) ----------
        const unsigned* E32 = (const unsigned*)s_E;       // row stride 36 u32
        int mt = w & 3;          // m-tile 0..3
        int nh = w >> 2;         // n half 0..1 (64 cols each)

        float hacc[8][4];
#pragma unroll
        for (int nt = 0; nt < 8; nt++)
#pragma unroll
            for (int r = 0; r < 4; r++) hacc[nt][r] = 0.f;

#pragma unroll
        for (int kt = 0; kt < 4; kt++) {
            unsigned a[4];
            int i0 = (mt * 16 + q) * 36 + kt * 8 + tg;
            a[0] = E32[i0];
            a[1] = E32[i0 + 8 * 36];
            a[2] = E32[i0 + 4];
            a[3] = E32[i0 + 8 * 36 + 4];
            int r0 = kt * 8 + tg;
#pragma unroll
            for (int nt = 0; nt < 8; nt++) {
                int ncol = nh * 64 + nt * 8 + q;
                unsigned b0 = s_W1p[r0 * 136 + ncol];
                unsigned b1 = s_W1p[(r0 + 4) * 136 + ncol];
                mma_fp16(hacc[nt], a, b0, b1);
            }
        }
        // silu + fp16 store to s_H
#pragma unroll
        for (int nt = 0; nt < 8; nt++) {
            int col = nh * 64 + nt * 8 + tg * 2;
            int row = mt * 16 + q;
            __half2 h01 = __floats2half2_rn(silu_f(hacc[nt][0]), silu_f(hacc[nt][1]));
            __half2 h23 = __floats2half2_rn(silu_f(hacc[nt][2]), silu_f(hacc[nt][3]));
            *(__half2*)&s_H[row * HSTR + col]       = h01;
            *(__half2*)&s_H[(row + 8) * HSTR + col] = h23;
        }
    }

    // ---------- phase C: TPW = H @ W2p, 2 chunks of 256 n-cols ----------
    unsigned* s_W2 = (unsigned*)base2;              // [64][WCHS]
    __half*   s_ep = (__half*)base2;                // epilogue staging [64][EPSTR]
    const unsigned* H32 = (const unsigned*)s_H;

    for (int nb = 0; nb < 2; nb++) {
        __syncthreads();    // phase B stores done / previous chunk copied out
        {
            const uint4* gp = ((const uint4*)g_W2p) + nb * 64;
            for (int i = tid; i < 64 * 64; i += 256) {
                int r = i >> 6, n4 = i & 63;
                ((uint4*)(s_W2 + r * WCHS))[n4] = gp[r * 128 + n4];
            }
        }
        __syncthreads();

        float acc[4][4][4];
#pragma unroll
        for (int mt = 0; mt < 4; mt++)
#pragma unroll
            for (int nt = 0; nt < 4; nt++)
#pragma unroll
                for (int r = 0; r < 4; r++) acc[mt][nt][r] = 0.f;

#pragma unroll
        for (int kt = 0; kt < 8; kt++) {
            unsigned a[4][4];
#pragma unroll
            for (int mt = 0; mt < 4; mt++) {
                int i0 = (mt * 16 + q) * (HSTR / 2) + kt * 8 + tg;
                a[mt][0] = H32[i0];
                a[mt][1] = H32[i0 + 8 * 68];
                a[mt][2] = H32[i0 + 4];
                a[mt][3] = H32[i0 + 8 * 68 + 4];
            }
            int r0 = kt * 8 + tg;
            unsigned b[4][2];
#pragma unroll
            for (int nt = 0; nt < 4; nt++) {
                int ncol = w * 32 + nt * 8 + q;
                b[nt][0] = s_W2[r0 * WCHS + ncol];
                b[nt][1] = s_W2[(r0 + 4) * WCHS + ncol];
            }
#pragma unroll
            for (int mt = 0; mt < 4; mt++)
#pragma unroll
                for (int nt = 0; nt < 4; nt++)
                    mma_fp16(acc[mt][nt], a[mt], b[nt][0], b[nt][1]);
        }

        __syncthreads();    // all warps done reading s_W2 -> reuse as staging
        // stage fp16 results in smem
#pragma unroll
        for (int nt = 0; nt < 4; nt++) {
            int col = w * 32 + nt * 8 + tg * 2;
#pragma unroll
            for (int mt = 0; mt < 4; mt++) {
                int row = mt * 16 + q;
                __half2 h01 = __floats2half2_rn(acc[mt][nt][0], acc[mt][nt][1]);
                __half2 h23 = __floats2half2_rn(acc[mt][nt][2], acc[mt][nt][3]);
                *(__half2*)&s_ep[row * EPSTR + col]       = h01;
                *(__half2*)&s_ep[(row + 8) * EPSTR + col] = h23;
            }
        }
        __syncthreads();
        // coalesced copy-out: 64 rows x 32 uint4 (512 B/row contiguous)
        for (int i = tid; i < 64 * 32; i += 256) {
            int r = i >> 5, n4 = i & 31;
            int row = e0 + r;
            if (row < E) {
                uint4 v = *(const uint4*)((const char*)s_ep + r * (EPSTR * 2) + n4 * 16);
                *(uint4*)&g_tpwh[(size_t)row * WOUT + nb * 256 + n4 * 8] = v;
            }
        }
    }
}

// ==================== per-dst gather (sync-light, edge-chunked) ====================

__global__ __launch_bounds__(128)
void gather_kernel(const float* __restrict__ xsrc,
                   const float* __restrict__ sh,
                   const int*   __restrict__ src,
                   float*       __restrict__ out) {
    int d = blockIdx.x;
    int c = threadIdx.x;   // 0..127
    __shared__ int   s_e[32];
    __shared__ int   s_s[32];
    __shared__ float s_shv[32 * SH_DIM];
    __shared__ float s_out[OUT_COLS];

    float acc[16];
#pragma unroll
    for (int i = 0; i < 16; i++) acc[i] = 0.f;

    int beg = g_offset[d], end = g_offset[d + 1];

    for (int base = beg; base < end; base += 32) {
        int cnt = min(32, end - base);
        __syncthreads();
        if (c < cnt) s_e[c] = g_elist[base + c];
        __syncthreads();
        if (c < cnt) s_s[c] = src[s_e[c]];
        for (int idx = c; idx < cnt * SH_DIM; idx += 128)
            s_shv[idx] = sh[(size_t)s_e[idx >> 4] * SH_DIM + (idx & 15)];
        __syncthreads();

#pragma unroll 4
        for (int j = 0; j < cnt; j++) {
            int e = s_e[j];
            int s = s_s[j];
            float xs = xsrc[(size_t)s * C_DIM + c];
            const __half* tp = &g_tpwh[(size_t)e * WOUT];
            float t0 = __half2float(tp[c])       * xs;
            float t1 = __half2float(tp[128 + c]) * xs;
            float t2 = __half2float(tp[256 + c]) * xs;
            float t3 = __half2float(tp[384 + c]) * xs;
            const float* sv = &s_shv[j * SH_DIM];
            acc[0] += t0 * sv[0];
#pragma unroll
            for (int m = 0; m < 3; m++) acc[1 + m] += t1 * sv[1 + m];
#pragma unroll
            for (int m = 0; m < 5; m++) acc[4 + m] += t2 * sv[4 + m];
#pragma unroll
            for (int m = 0; m < 7; m++) acc[9 + m] += t3 * sv[9 + m];
        }
    }

    __syncthreads();
    s_out[c] = acc[0];
#pragma unroll
    for (int m = 0; m < 3; m++) s_out[128  + c * 3 + m] = acc[1 + m];
#pragma unroll
    for (int m = 0; m < 5; m++) s_out[512  + c * 5 + m] = acc[4 + m];
#pragma unroll
    for (int m = 0; m < 7; m++) s_out[1152 + c * 7 + m] = acc[9 + m];
    __syncthreads();

    float4* o4 = (float4*)(out + (size_t)d * OUT_COLS);
    const float4* s4 = (const float4*)s_out;
    for (int i = c; i < OUT_COLS / 4; i += 128) o4[i] = s4[i];
}

// ==================== launch ====================

extern "C" void kernel_launch(void* const* d_in, const int* in_sizes, int n_in,
                              void* d_out, int out_size) {
    const float* xsrc = (const float*)d_in[0];
    const float* sh   = (const float*)d_in[1];
    const float* emb  = (const float*)d_in[2];
    const float* W1   = (const float*)d_in[3];
    const float* W2   = (const float*)d_in[4];
    const int*   src  = (const int*)d_in[5];
    const int*   dst  = (const int*)d_in[6];

    int E  = in_sizes[5];
    int nd = out_size / OUT_COLS;

    zero_kernel<<<(nd + 255) / 256, 256>>>(nd);
    hist_kernel<<<(E + 255) / 256, 256>>>(dst, E);
    scan_kernel<<<1, 1024>>>(nd);
    fill_kernel<<<(E + 255) / 256, 256>>>(dst, E);
    pack_kernel<<<(64 * WOUT + 255) / 256, 256>>>(W1, W2);

    cudaFuncSetAttribute(mlp_kernel, cudaFuncAttributeMaxDynamicSharedMemorySize, SMEM_BYTES);
    mlp_kernel<<<(E + EPB - 1) / EPB, 256, SMEM_BYTES>>>(emb, E);

    gather_kernel<<<nd, 128>>>(xsrc, sh, src, (float*)d_out);
}